// round 3
// baseline (speedup 1.0000x reference)
#include <cuda_runtime.h>
#include <cuda_bf16.h>
#include <cstdint>

#define L   1024
#define CZ  128
#define TLL 64
#define TMM 64
#define NT  16   // L / TLL

// ---------------- scratch (__device__ globals; no allocation) ----------------
__device__ float g_PartC[(size_t)NT * L * CZ];   // [m_tile][l][c] partial col sums (8 MB)
__device__ float g_PartR[(size_t)NT * L * CZ];   // [l_tile][m][c] partial row sums (8 MB)
__device__ float g_maskC[L];
__device__ float g_maskR[L];
__device__ float g_ssc[L * CZ];
__device__ float g_ssr[L * CZ];

// ---------------- mask sums ----------------
__global__ void k_masksums(const float* __restrict__ mask) {
  __shared__ float red[2][256];
  int i = blockIdx.x, tid = threadIdx.x;
  float sc = 0.f, sr = 0.f;
  for (int j = tid; j < L; j += 256) {
    sc += mask[(size_t)i * L + j];
    sr += mask[(size_t)j * L + i];
  }
  red[0][tid] = sc; red[1][tid] = sr;
  __syncthreads();
  for (int s = 128; s > 0; s >>= 1) {
    if (tid < s) { red[0][tid] += red[0][tid + s]; red[1][tid] += red[1][tid + s]; }
    __syncthreads();
  }
  if (tid == 0) { g_maskC[i] = red[0][0]; g_maskR[i] = red[1][0]; }
}

// ---------------- stage 1: fused LN + GEMM(w1) + relu*mask + partial reductions ----------------
__global__ __launch_bounds__(256) void k_stage1(
    const float* __restrict__ s_z, const float* __restrict__ mask,
    const float* __restrict__ ln_g, const float* __restrict__ ln_b,
    const float* __restrict__ w1, const float* __restrict__ b1) {
  extern __shared__ char smem_raw[];
  __nv_bfloat16* sW     = (__nv_bfloat16*)smem_raw;      // [128][136] w1 bf16
  __nv_bfloat16* sA     = sW + 128 * 136;                // [64][136] normalized z tile
  float*         sMaskT = (float*)(sA + 64 * 136);       // [64][68] mask tile
  float*         sRow   = sMaskT + 64 * 68;              // [128] per-iter row sum
  float*         sG     = sRow + 128;                    // [128]
  float*         sB     = sG + 128;                      // [128]

  const int tid = threadIdx.x, lane = tid & 31, warp = tid >> 5;
  const int g = lane >> 2, q = lane & 3;
  const int warp_m = warp >> 1, warp_n = warp & 1;       // 4 x 2 warp grid
  const int bx = blockIdx.x, by = blockIdx.y;
  const int m0 = bx * TMM, l0 = by * TLL;
  const int arow = warp_m * 16;

  // load w1 -> SMEM bf16, [d][c]
  for (int i = tid; i < 128 * 128; i += 256) {
    int d = i >> 7, c = i & 127;
    sW[d * 136 + c] = __float2bfloat16(w1[i]);
  }
  if (tid < 128) { sG[tid] = ln_g[tid]; sB[tid] = ln_b[tid]; }
  // load 64x64 mask tile
  for (int i = tid; i < 64 * 16; i += 256) {
    int r = i >> 4, c4 = (i & 15) << 2;
    float4 mv = *(const float4*)(mask + (size_t)(l0 + r) * L + m0 + c4);
    *(float4*)(sMaskT + r * 68 + c4) = mv;
  }

  // b1 values at this thread's accumulator columns
  float b1v[16];
  #pragma unroll
  for (int nb = 0; nb < 8; nb++) {
    int col = warp_n * 64 + nb * 8 + q * 2;
    b1v[nb * 2] = b1[col]; b1v[nb * 2 + 1] = b1[col + 1];
  }
  float colAcc[32];
  #pragma unroll
  for (int i = 0; i < 32; i++) colAcc[i] = 0.f;

  __syncthreads();

  for (int mi = 0; mi < TMM; mi++) {
    const int m = m0 + mi;
    if (tid < 128) sRow[tid] = 0.f;

    // --- LayerNorm: each warp handles 8 rows (l values), one 128-vector per row ---
    {
      float4 vv[8];
      #pragma unroll
      for (int r8 = 0; r8 < 8; r8++) {
        int l = l0 + warp * 8 + r8;
        vv[r8] = *(const float4*)(s_z + ((size_t)l * L + m) * CZ + lane * 4);
      }
      #pragma unroll
      for (int r8 = 0; r8 < 8; r8++) {
        float4 v = vv[r8];
        float s  = v.x + v.y + v.z + v.w;
        float s2 = v.x * v.x + v.y * v.y + v.z * v.z + v.w * v.w;
        #pragma unroll
        for (int o = 16; o > 0; o >>= 1) {
          s  += __shfl_xor_sync(0xffffffffu, s, o);
          s2 += __shfl_xor_sync(0xffffffffu, s2, o);
        }
        float mu  = s * (1.f / 128.f);
        float var = fmaf(s2, 1.f / 128.f, -mu * mu);
        float rs  = rsqrtf(var + 1e-5f);
        int c0 = lane * 4;
        float f0 = (v.x - mu) * rs * sG[c0]     + sB[c0];
        float f1 = (v.y - mu) * rs * sG[c0 + 1] + sB[c0 + 1];
        float f2 = (v.z - mu) * rs * sG[c0 + 2] + sB[c0 + 2];
        float f3 = (v.w - mu) * rs * sG[c0 + 3] + sB[c0 + 3];
        __nv_bfloat162 p0 = __floats2bfloat162_rn(f0, f1);
        __nv_bfloat162 p1 = __floats2bfloat162_rn(f2, f3);
        uint2 pk = make_uint2(*(uint32_t*)&p0, *(uint32_t*)&p1);
        *(uint2*)(sA + (warp * 8 + r8) * 136 + c0) = pk;
      }
    }
    __syncthreads();

    // --- GEMM: h[64 x 128] = sA @ sW^T, bf16 mma.sync, warp tile 16x64 ---
    float acc[32];
    #pragma unroll
    for (int i = 0; i < 32; i++) acc[i] = 0.f;
    #pragma unroll
    for (int ks = 0; ks < 8; ks++) {
      const int k0 = ks * 16;
      uint32_t a0 = *(const uint32_t*)(sA + (arow + g    ) * 136 + k0     + q * 2);
      uint32_t a1 = *(const uint32_t*)(sA + (arow + g + 8) * 136 + k0     + q * 2);
      uint32_t a2 = *(const uint32_t*)(sA + (arow + g    ) * 136 + k0 + 8 + q * 2);
      uint32_t a3 = *(const uint32_t*)(sA + (arow + g + 8) * 136 + k0 + 8 + q * 2);
      #pragma unroll
      for (int nb = 0; nb < 8; nb++) {
        const int n = warp_n * 64 + nb * 8 + g;
        uint32_t bb0 = *(const uint32_t*)(sW + n * 136 + k0     + q * 2);
        uint32_t bb1 = *(const uint32_t*)(sW + n * 136 + k0 + 8 + q * 2);
        asm volatile(
          "mma.sync.aligned.m16n8k16.row.col.f32.bf16.bf16.f32 "
          "{%0,%1,%2,%3}, {%4,%5,%6,%7}, {%8,%9}, {%0,%1,%2,%3};\n"
          : "+f"(acc[nb*4+0]), "+f"(acc[nb*4+1]), "+f"(acc[nb*4+2]), "+f"(acc[nb*4+3])
          : "r"(a0), "r"(a1), "r"(a2), "r"(a3), "r"(bb0), "r"(bb1));
      }
    }

    // --- epilogue: bias, relu, mask; accumulate col sums (regs) + row sums (shuffle+smem) ---
    float mk0 = sMaskT[(arow + g    ) * 68 + mi];
    float mk1 = sMaskT[(arow + g + 8) * 68 + mi];
    float rsum[16];
    #pragma unroll
    for (int nb = 0; nb < 8; nb++) {
      float h0 = fmaxf(acc[nb*4+0] + b1v[nb*2+0], 0.f) * mk0;
      float h1 = fmaxf(acc[nb*4+1] + b1v[nb*2+1], 0.f) * mk0;
      float h2 = fmaxf(acc[nb*4+2] + b1v[nb*2+0], 0.f) * mk1;
      float h3 = fmaxf(acc[nb*4+3] + b1v[nb*2+1], 0.f) * mk1;
      colAcc[nb*4+0] += h0; colAcc[nb*4+1] += h1;
      colAcc[nb*4+2] += h2; colAcc[nb*4+3] += h3;
      rsum[nb*2+0] = h0 + h2;
      rsum[nb*2+1] = h1 + h3;
    }
    #pragma unroll
    for (int off = 4; off < 32; off <<= 1) {
      #pragma unroll
      for (int i2 = 0; i2 < 16; i2++)
        rsum[i2] += __shfl_xor_sync(0xffffffffu, rsum[i2], off);
    }
    if (lane < 4) {
      #pragma unroll
      for (int nb = 0; nb < 8; nb++) {
        atomicAdd(&sRow[warp_n * 64 + nb * 8 + lane * 2    ], rsum[nb*2+0]);
        atomicAdd(&sRow[warp_n * 64 + nb * 8 + lane * 2 + 1], rsum[nb*2+1]);
      }
    }
    __syncthreads();
    if (tid < 128)
      g_PartR[((size_t)by * L + m) * CZ + tid] = sRow[tid];
    // safe: only tid<128 touch sRow between here and the atomics after next barrier
  }

  // write column partials
  #pragma unroll
  for (int nb = 0; nb < 8; nb++) {
    int col = warp_n * 64 + nb * 8 + q * 2;
    int r0 = arow + g, r1 = r0 + 8;
    size_t base = (size_t)bx * L * CZ;
    g_PartC[base + (size_t)(l0 + r0) * CZ + col    ] = colAcc[nb*4+0];
    g_PartC[base + (size_t)(l0 + r0) * CZ + col + 1] = colAcc[nb*4+1];
    g_PartC[base + (size_t)(l0 + r1) * CZ + col    ] = colAcc[nb*4+2];
    g_PartC[base + (size_t)(l0 + r1) * CZ + col + 1] = colAcc[nb*4+3];
  }
}

// ---------------- stage 2: reduce partials, apply w2/b2, normalize ----------------
__global__ void k_stage2(const float* __restrict__ w2, const float* __restrict__ b2) {
  __shared__ float sv[128];
  const int i = blockIdx.x, tid = threadIdx.x;
  {
    float a = 0.f;
    #pragma unroll
    for (int t = 0; t < NT; t++) a += g_PartC[((size_t)t * L + i) * CZ + tid];
    sv[tid] = a;
    __syncthreads();
    float mc = g_maskC[i];
    const float4* wr = (const float4*)(w2 + tid * 128);
    float dot = 0.f;
    #pragma unroll 8
    for (int c = 0; c < 32; c++) {
      float4 wv = wr[c];
      dot += sv[c*4] * wv.x + sv[c*4+1] * wv.y + sv[c*4+2] * wv.z + sv[c*4+3] * wv.w;
    }
    g_ssc[i * CZ + tid] = (dot + b2[tid] * mc) / fmaxf(mc, 1.f);
    __syncthreads();
  }
  {
    float a = 0.f;
    #pragma unroll
    for (int t = 0; t < NT; t++) a += g_PartR[((size_t)t * L + i) * CZ + tid];
    sv[tid] = a;
    __syncthreads();
    float mr = g_maskR[i];
    const float4* wr = (const float4*)(w2 + tid * 128);
    float dot = 0.f;
    #pragma unroll 8
    for (int c = 0; c < 32; c++) {
      float4 wv = wr[c];
      dot += sv[c*4] * wv.x + sv[c*4+1] * wv.y + sv[c*4+2] * wv.z + sv[c*4+3] * wv.w;
    }
    g_ssr[i * CZ + tid] = (dot + b2[tid] * mr) / fmaxf(mr, 1.f);
  }
}

// ---------------- stage 3: out = cat @ wc^T + bc, tf32 mma ----------------
__device__ __forceinline__ uint32_t f2tf(float x) {
  uint32_t r; asm("cvt.rna.tf32.f32 %0, %1;" : "=r"(r) : "f"(x)); return r;
}

__global__ __launch_bounds__(256) void k_stage3(
    const float* __restrict__ s_s_in, const float* __restrict__ wc,
    const float* __restrict__ bc, float* __restrict__ out) {
  __shared__ uint32_t sA3[128 * 33];
  __shared__ uint32_t sB3[128 * 33];
  const int tid = threadIdx.x, lane = tid & 31, warp = tid >> 5;
  const int g = lane >> 2, q = lane & 3;
  const int warp_m = warp >> 1, warp_n = warp & 1;   // 4 x 2, warp tile 32x64
  const int t0 = blockIdx.y * 128, d0 = blockIdx.x * 128;

  float acc[2][8][4];
  #pragma unroll
  for (int a = 0; a < 2; a++)
    #pragma unroll
    for (int b = 0; b < 8; b++)
      #pragma unroll
      for (int c = 0; c < 4; c++) acc[a][b][c] = 0.f;

  for (int kc = 0; kc < 40; kc++) {
    const float* srcb; int stride, koff;
    if (kc < 4)      { srcb = g_ssc;  stride = 128;  koff = kc * 32; }
    else if (kc < 8) { srcb = g_ssr;  stride = 128;  koff = (kc - 4) * 32; }
    else             { srcb = s_s_in; stride = 1024; koff = (kc - 8) * 32; }
    #pragma unroll
    for (int it = 0; it < 4; it++) {
      int row = (tid >> 3) + it * 32;
      int kk  = (tid & 7) * 4;
      float4 av = *(const float4*)(srcb + (size_t)(t0 + row) * stride + koff + kk);
      sA3[row * 33 + kk + 0] = f2tf(av.x);
      sA3[row * 33 + kk + 1] = f2tf(av.y);
      sA3[row * 33 + kk + 2] = f2tf(av.z);
      sA3[row * 33 + kk + 3] = f2tf(av.w);
      float4 bv = *(const float4*)(wc + (size_t)(d0 + row) * 1280 + kc * 32 + kk);
      sB3[row * 33 + kk + 0] = f2tf(bv.x);
      sB3[row * 33 + kk + 1] = f2tf(bv.y);
      sB3[row * 33 + kk + 2] = f2tf(bv.z);
      sB3[row * 33 + kk + 3] = f2tf(bv.w);
    }
    __syncthreads();
    #pragma unroll
    for (int ks = 0; ks < 4; ks++) {
      const int k0 = ks * 8;
      uint32_t afr[2][4];
      #pragma unroll
      for (int mt = 0; mt < 2; mt++) {
        int r = warp_m * 32 + mt * 16 + g;
        afr[mt][0] = sA3[r * 33 + k0 + q];
        afr[mt][1] = sA3[(r + 8) * 33 + k0 + q];
        afr[mt][2] = sA3[r * 33 + k0 + q + 4];
        afr[mt][3] = sA3[(r + 8) * 33 + k0 + q + 4];
      }
      #pragma unroll
      for (int nt = 0; nt < 8; nt++) {
        int n = warp_n * 64 + nt * 8 + g;
        uint32_t bb0 = sB3[n * 33 + k0 + q];
        uint32_t bb1 = sB3[n * 33 + k0 + q + 4];
        #pragma unroll
        for (int mt = 0; mt < 2; mt++) {
          asm volatile(
            "mma.sync.aligned.m16n8k8.row.col.f32.tf32.tf32.f32 "
            "{%0,%1,%2,%3}, {%4,%5,%6,%7}, {%8,%9}, {%0,%1,%2,%3};\n"
            : "+f"(acc[mt][nt][0]), "+f"(acc[mt][nt][1]),
              "+f"(acc[mt][nt][2]), "+f"(acc[mt][nt][3])
            : "r"(afr[mt][0]), "r"(afr[mt][1]), "r"(afr[mt][2]), "r"(afr[mt][3]),
              "r"(bb0), "r"(bb1));
        }
      }
    }
    __syncthreads();
  }

  #pragma unroll
  for (int mt = 0; mt < 2; mt++) {
    int r = t0 + warp_m * 32 + mt * 16 + g;
    #pragma unroll
    for (int nt = 0; nt < 8; nt++) {
      int c = d0 + warp_n * 64 + nt * 8 + q * 2;
      float bc0 = bc[c], bc1 = bc[c + 1];
      out[(size_t)r * L + c]           = acc[mt][nt][0] + bc0;
      out[(size_t)r * L + c + 1]       = acc[mt][nt][1] + bc1;
      out[(size_t)(r + 8) * L + c]     = acc[mt][nt][2] + bc0;
      out[(size_t)(r + 8) * L + c + 1] = acc[mt][nt][3] + bc1;
    }
  }
}

// ---------------- launch ----------------
extern "C" void kernel_launch(void* const* d_in, const int* in_sizes, int n_in,
                              void* d_out, int out_size) {
  const float* s_z    = (const float*)d_in[0];
  const float* s_s_in = (const float*)d_in[1];
  const float* pmask  = (const float*)d_in[2];
  const float* ln_g   = (const float*)d_in[3];
  const float* ln_b   = (const float*)d_in[4];
  const float* w1     = (const float*)d_in[5];
  const float* b1     = (const float*)d_in[6];
  const float* w2     = (const float*)d_in[7];
  const float* b2     = (const float*)d_in[8];
  const float* wc     = (const float*)d_in[9];
  const float* bc     = (const float*)d_in[10];
  float* out = (float*)d_out;

  const int smem1 = (128 * 136 + 64 * 136) * 2 + (64 * 68 + 128 + 128 + 128) * 4; // 71168 B
  cudaFuncSetAttribute(k_stage1, cudaFuncAttributeMaxDynamicSharedMemorySize, smem1);

  k_masksums<<<L, 256>>>(pmask);
  k_stage1<<<dim3(NT, NT), 256, smem1>>>(s_z, pmask, ln_g, ln_b, w1, b1);
  k_stage2<<<L, 128>>>(w2, b2);
  k_stage3<<<dim3(8, 8), 256>>>(s_s_in, wc, bc, out);
}